// round 4
// baseline (speedup 1.0000x reference)
#include <cuda_runtime.h>
#include <math.h>

// Problem shape (fixed)
#define Bv 4
#define Hv 256
#define Wv 256
#define CH 32
#define NPIX (Bv*Hv*Wv)          // 262144
#define KK 81
#define NB 10

// LCV tile config (pixel-pair threads: 128 threads -> 32x8 pixels)
#define HALO 4
#define TBX 32
#define TBY 8
#define TW 40                    // TBX + 2*HALO
#define TH 16                    // TBY + 2*HALO
#define PLANE (TW*TH)            // 640

typedef unsigned long long ull;

// Static device scratch (no runtime allocation allowed)
__device__ float g_w[(size_t)NPIX * CH];
__device__ float g_mapped[(size_t)NPIX * CH];
__device__ float g_fg[(size_t)NPIX * CH];
__device__ float g_c[(size_t)KK * NPIX];     // cost volume of w (maintained via linearity)
__device__ float g_s[(size_t)KK * NPIX];     // LCV(fg, ref)
__device__ float g_cv2[(size_t)KK * NPIX];   // LCV(mapped, ref)
__device__ float g_alpha[NPIX];              // alpha * step_length
__device__ float g_A1[KK], g_A2[KK], g_Y[KK];
__device__ float g_scal[2];                  // [0]=reg_weight, [1]=step_length

// ---------------- f32x2 helpers ----------------
__device__ __forceinline__ ull ffma2(ull a, ull b, ull c) {
    ull d; asm("fma.rn.f32x2 %0, %1, %2, %3;" : "=l"(d) : "l"(a), "l"(b), "l"(c)); return d;
}
__device__ __forceinline__ ull pack2(float x, float y) {
    ull d; asm("mov.b64 %0, {%1, %2};" : "=l"(d) : "f"(x), "f"(y)); return d;
}
__device__ __forceinline__ float2 unpack2(ull a) {
    float2 r; asm("mov.b64 {%0, %1}, %2;" : "=f"(r.x), "=f"(r.y) : "l"(a)); return r;
}
__device__ __forceinline__ ull lds64(unsigned addr) {
    ull d; asm("ld.shared.b64 %0, [%1];" : "=l"(d) : "r"(addr)); return d;
}
__device__ __forceinline__ unsigned smem_u32(const void* p) {
    unsigned a;
    asm("{ .reg .u64 t; cvta.to.shared.u64 t, %1; cvt.u32.u64 %0, t; }" : "=r"(a) : "l"(p));
    return a;
}
__device__ __forceinline__ float sgnf(float x) {
    return (x > 0.f ? 1.f : 0.f) - (x < 0.f ? 1.f : 0.f);
}

// ---------------------------------------------------------------------------
// Setup: per-k constants. A1 = vp*(1-a)/2, A2 = vp*(1+a)/2, Y = vp*y
// ---------------------------------------------------------------------------
__global__ void setup_consts(const float* __restrict__ tw,
                             const float* __restrict__ sw,
                             const float* __restrict__ mw,
                             const float* __restrict__ wreg,
                             const float* __restrict__ lstep) {
    int k = threadIdx.x;
    if (k < KK) {
        int i = k / 9, j = k % 9;
        float di = (float)(i - 4), dj = (float)(j - 4);
        float dist = sqrtf(di * di + dj * dj);
        float y = 0.f, vp = 0.f, m = 0.f;
        #pragma unroll
        for (int b = 0; b < NB; b++) {
            float t = dist * 2.0f - (float)b;
            float bv;
            if (i < 8) bv = fmaxf(0.f, 1.f - fabsf(t));
            else       bv = fminf(fmaxf(1.f + t, 0.f), 1.f);   // row-8 clip quirk
            y  += bv * tw[b];
            vp += bv * sw[b];
            m  += bv * mw[b];
        }
        float a = 1.f / (1.f + expf(-m));   // sigmoid(mask)
        g_A1[k] = vp * 0.5f * (1.f - a);
        g_A2[k] = vp * 0.5f * (1.f + a);
        g_Y[k]  = vp * y;
    } else if (k == KK) {
        float r  = wreg[0] * wreg[0];
        float lo = (1e-5f * 1e-5f) / ((float)CH * (float)CH);
        g_scal[0] = fmaxf(r, lo);
        g_scal[1] = expf(lstep[0]);
    }
}

// ---------------------------------------------------------------------------
// w0 = beta * ref / (mean(ref^2) + 1e-6)
// ---------------------------------------------------------------------------
__global__ void init_w(const float* __restrict__ ref, const float* __restrict__ beta) {
    int p = blockIdx.x * blockDim.x + threadIdx.x;
    if (p >= NPIX) return;
    const float4* rp = (const float4*)(ref + (size_t)p * CH);
    float4 v[8];
    float ss = 0.f;
    #pragma unroll
    for (int i = 0; i < 8; i++) {
        v[i] = rp[i];
        ss += v[i].x * v[i].x + v[i].y * v[i].y + v[i].z * v[i].z + v[i].w * v[i].w;
    }
    float sc = beta[0] / (ss * (1.f / (float)CH) + 1e-6f);
    float4* wp = (float4*)(g_w + (size_t)p * CH);
    #pragma unroll
    for (int i = 0; i < 8; i++) {
        v[i].x *= sc; v[i].y *= sc; v[i].z *= sc; v[i].w *= sc;
        wp[i] = v[i];
    }
}

extern __shared__ float sdyn[];

// ---------------------------------------------------------------------------
// k_lcv<MODE>: out[k][pix] = LCV(src, ref)  (scaled by 1/CH)
// Pixel-pair threads, f32x2 math, register row reuse (5 LDS.64 per (c,di)
// serve all 9 column shifts of both pixels).
// MODE 0: plain.
// MODE 1: + alpha/update (src == fg): den from dact(sgn(g_c)); num = sum fg^2;
//         alpha = num/den*step; w' = w + alpha*fg -> wout; store alpha; write s.
// MODE 2: like 1 but last iteration: skip alpha/s stores, write w' to wout.
// ---------------------------------------------------------------------------
template<int MODE>
__global__ void __launch_bounds__(128)
k_lcv(const float* __restrict__ src, const float* __restrict__ ref,
      float* __restrict__ out, float* __restrict__ wout) {
    float* Rs = sdyn;                       // CH * PLANE floats (80KB)
    float* sA1 = sdyn + CH * PLANE;         // (MODE>0) 81
    float* sA2 = sA1 + KK;                  // 81

    const int tid = threadIdx.x;
    const int b = blockIdx.z, y0 = blockIdx.y * TBY, x0 = blockIdx.x * TBX;

    // ---- load halo tile (channel-planar, row stride TW=40) ----
    #pragma unroll
    for (int j = 0; j < PLANE / 128; j++) {     // 5
        int pix = tid + j * 128;
        int py = pix / TW, px = pix - py * TW;
        int gy = y0 - HALO + py, gx = x0 - HALO + px;
        bool ok = ((unsigned)gy < (unsigned)Hv) && ((unsigned)gx < (unsigned)Wv);
        const float4* rp = ok ? (const float4*)(ref + (((size_t)(b * Hv + gy) * Wv) + gx) * CH)
                              : (const float4*)ref;
        #pragma unroll
        for (int q = 0; q < 8; q++) {
            float4 v = ok ? rp[q] : make_float4(0.f, 0.f, 0.f, 0.f);
            if (!ok) { v.x = v.y = v.z = v.w = 0.f; }
            Rs[(4 * q + 0) * PLANE + pix] = v.x;
            Rs[(4 * q + 1) * PLANE + pix] = v.y;
            Rs[(4 * q + 2) * PLANE + pix] = v.z;
            Rs[(4 * q + 3) * PLANE + pix] = v.w;
        }
    }
    if (MODE > 0 && tid < KK) {
        sA1[tid] = g_A1[tid];
        sA2[tid] = g_A2[tid];
    }
    __syncthreads();

    const int txp = tid & 15;               // pair column 0..15
    const int ty  = tid >> 4;               // row 0..7
    const int p0  = (b * Hv + (y0 + ty)) * Wv + (x0 + 2 * txp);   // even

    // ---- load src for the pixel pair, pack per-channel f32x2 ----
    ull w2r[CH];
    float numx = 0.f, numy = 0.f;
    {
        const float4* s4 = (const float4*)(src + (size_t)p0 * CH);
        #pragma unroll
        for (int q = 0; q < 8; q++) {
            float4 a = s4[q];       // pixel p0, channels 4q..4q+3
            float4 c = s4[q + 8];   // pixel p0+1
            w2r[4 * q + 0] = pack2(a.x, c.x);
            w2r[4 * q + 1] = pack2(a.y, c.y);
            w2r[4 * q + 2] = pack2(a.z, c.z);
            w2r[4 * q + 3] = pack2(a.w, c.w);
            if (MODE > 0) {
                numx += a.x * a.x + a.y * a.y + a.z * a.z + a.w * a.w;
                numy += c.x * c.x + c.y * c.y + c.z * c.z + c.w * c.w;
            }
        }
    }

    const unsigned rs_base = smem_u32(Rs);
    const float inv = 1.f / (float)CH;
    float denx = 0.f, deny = 0.f;

    for (int di = 0; di < 9; di++) {
        ull acc[9];
        #pragma unroll
        for (int o = 0; o < 9; o++) acc[o] = 0ull;

        unsigned rb = rs_base + (unsigned)(((ty + di) * TW + 2 * txp) * 4);
        #pragma unroll 4
        for (int c = 0; c < CH; c++) {
            unsigned a = rb + (unsigned)(c * PLANE * 4);
            ull p0v = lds64(a);
            ull p1v = lds64(a + 8);
            ull p2v = lds64(a + 16);
            ull p3v = lds64(a + 24);
            ull p4v = lds64(a + 32);
            ull wv = w2r[c];
            acc[0] = ffma2(wv, p0v, acc[0]);
            acc[2] = ffma2(wv, p1v, acc[2]);
            acc[4] = ffma2(wv, p2v, acc[4]);
            acc[6] = ffma2(wv, p3v, acc[6]);
            acc[8] = ffma2(wv, p4v, acc[8]);
            float2 f0 = unpack2(p0v), f1 = unpack2(p1v), f2 = unpack2(p2v);
            float2 f3 = unpack2(p3v), f4 = unpack2(p4v);
            acc[1] = ffma2(wv, pack2(f0.y, f1.x), acc[1]);
            acc[3] = ffma2(wv, pack2(f1.y, f2.x), acc[3]);
            acc[5] = ffma2(wv, pack2(f2.y, f3.x), acc[5]);
            acc[7] = ffma2(wv, pack2(f3.y, f4.x), acc[7]);
        }

        #pragma unroll
        for (int o = 0; o < 9; o++) {
            int k = di * 9 + o;
            float2 r = unpack2(acc[o]);
            r.x *= inv; r.y *= inv;
            if (MODE == 0 || MODE == 1)
                *(float2*)(out + (size_t)k * NPIX + p0) = r;
            if (MODE > 0) {
                float2 cc = *(const float2*)(g_c + (size_t)k * NPIX + p0);
                float a1 = sA1[k], a2 = sA2[k];
                float d0 = a1 * sgnf(cc.x) + a2;
                float d1 = a1 * sgnf(cc.y) + a2;
                float t0 = d0 * r.x, t1 = d1 * r.y;
                denx += t0 * t0;
                deny += t1 * t1;
            }
        }
    }

    if (MODE > 0) {
        float st = g_scal[1];
        float as0 = numx / denx * st;
        float as1 = numy / deny * st;
        if (MODE == 1)
            *(float2*)(g_alpha + p0) = make_float2(as0, as1);
        const float4* w4 = (const float4*)(g_w + (size_t)p0 * CH);
        float4* o4 = (float4*)(wout + (size_t)p0 * CH);
        #pragma unroll
        for (int q = 0; q < 8; q++) {
            float4 wv = w4[q];
            float2 fa = unpack2(w2r[4 * q + 0]);
            float2 fb = unpack2(w2r[4 * q + 1]);
            float2 fc = unpack2(w2r[4 * q + 2]);
            float2 fd = unpack2(w2r[4 * q + 3]);
            wv.x += as0 * fa.x; wv.y += as0 * fb.x; wv.z += as0 * fc.x; wv.w += as0 * fd.x;
            o4[q] = wv;
            float4 wv2 = w4[q + 8];
            wv2.x += as1 * fa.y; wv2.y += as1 * fb.y; wv2.z += as1 * fc.y; wv2.w += as1 * fd.y;
            o4[q + 8] = wv2;
        }
    }
}

// ---------------------------------------------------------------------------
// k_act_fold: (optionally c += alpha*s, written back); sv = dact*(act - Y);
//             mapped = sv @ mr_w + mr_b.  Pixel-pair threads, f32x2 fold.
// ---------------------------------------------------------------------------
template<int UPDATE>
__global__ void __launch_bounds__(256)
k_act_fold(const float* __restrict__ M, const float* __restrict__ bias,
           float* __restrict__ dst) {
    __shared__ float sM[KK * CH];      // read as float2 pairs
    __shared__ float sA1[KK], sA2[KK], sY[KK];
    for (int e = threadIdx.x; e < KK * CH; e += 256) sM[e] = __ldg(M + e);
    if (threadIdx.x < KK) {
        sA1[threadIdx.x] = g_A1[threadIdx.x];
        sA2[threadIdx.x] = g_A2[threadIdx.x];
        sY[threadIdx.x]  = g_Y[threadIdx.x];
    }
    __syncthreads();

    int t = blockIdx.x * 256 + threadIdx.x;
    int p0 = 2 * t;
    const unsigned m_base = smem_u32(sM);

    ull macc0[CH / 2], macc1[CH / 2];
    #pragma unroll
    for (int cp = 0; cp < CH / 2; cp++) {
        float b0 = __ldg(bias + 2 * cp), b1 = __ldg(bias + 2 * cp + 1);
        macc0[cp] = pack2(b0, b1);
        macc1[cp] = pack2(b0, b1);
    }
    float2 as2 = make_float2(0.f, 0.f);
    if (UPDATE) as2 = *(const float2*)(g_alpha + p0);

    for (int k = 0; k < KK; k++) {
        float2 cc = *(const float2*)(g_c + (size_t)k * NPIX + p0);
        if (UPDATE) {
            float2 ss = *(const float2*)(g_s + (size_t)k * NPIX + p0);
            cc.x += as2.x * ss.x;
            cc.y += as2.y * ss.y;
            *(float2*)(g_c + (size_t)k * NPIX + p0) = cc;
        }
        float a1 = sA1[k], a2 = sA2[k], yk = sY[k];
        float sv0 = (a1 * sgnf(cc.x) + a2) * (a1 * fabsf(cc.x) + a2 * cc.x - yk);
        float sv1 = (a1 * sgnf(cc.y) + a2) * (a1 * fabsf(cc.y) + a2 * cc.y - yk);
        ull v0 = pack2(sv0, sv0);
        ull v1 = pack2(sv1, sv1);
        unsigned mk = m_base + (unsigned)(k * CH * 4);
        #pragma unroll
        for (int cp = 0; cp < CH / 2; cp++) {
            ull m2 = lds64(mk + cp * 8);
            macc0[cp] = ffma2(v0, m2, macc0[cp]);
            macc1[cp] = ffma2(v1, m2, macc1[cp]);
        }
    }

    #pragma unroll
    for (int cp = 0; cp < CH / 2; cp++) {
        *(float2*)(dst + (size_t)p0 * CH + 2 * cp)      = unpack2(macc0[cp]);
        *(float2*)(dst + (size_t)(p0 + 1) * CH + 2 * cp) = unpack2(macc1[cp]);
    }
}

// ---------------------------------------------------------------------------
// k_foldB: fg = reg_weight * w + cv2 @ lr_w + lr_b
// ---------------------------------------------------------------------------
__global__ void __launch_bounds__(256)
k_foldB(const float* __restrict__ M, const float* __restrict__ bias) {
    __shared__ float sM[KK * CH];
    for (int e = threadIdx.x; e < KK * CH; e += 256) sM[e] = __ldg(M + e);
    __syncthreads();

    int t = blockIdx.x * 256 + threadIdx.x;
    int p0 = 2 * t;
    const unsigned m_base = smem_u32(sM);

    ull macc0[CH / 2], macc1[CH / 2];
    #pragma unroll
    for (int cp = 0; cp < CH / 2; cp++) {
        float b0 = __ldg(bias + 2 * cp), b1 = __ldg(bias + 2 * cp + 1);
        macc0[cp] = pack2(b0, b1);
        macc1[cp] = pack2(b0, b1);
    }

    for (int k = 0; k < KK; k++) {
        float2 cc = *(const float2*)(g_cv2 + (size_t)k * NPIX + p0);
        ull v0 = pack2(cc.x, cc.x);
        ull v1 = pack2(cc.y, cc.y);
        unsigned mk = m_base + (unsigned)(k * CH * 4);
        #pragma unroll
        for (int cp = 0; cp < CH / 2; cp++) {
            ull m2 = lds64(mk + cp * 8);
            macc0[cp] = ffma2(v0, m2, macc0[cp]);
            macc1[cp] = ffma2(v1, m2, macc1[cp]);
        }
    }

    float reg = g_scal[0];
    #pragma unroll
    for (int cp = 0; cp < CH / 2; cp++) {
        float2 w0 = *(const float2*)(g_w + (size_t)p0 * CH + 2 * cp);
        float2 w1 = *(const float2*)(g_w + (size_t)(p0 + 1) * CH + 2 * cp);
        float2 m0 = unpack2(macc0[cp]);
        float2 m1 = unpack2(macc1[cp]);
        m0.x += reg * w0.x; m0.y += reg * w0.y;
        m1.x += reg * w1.x; m1.y += reg * w1.y;
        *(float2*)(g_fg + (size_t)p0 * CH + 2 * cp)      = m0;
        *(float2*)(g_fg + (size_t)(p0 + 1) * CH + 2 * cp) = m1;
    }
}

// ---------------------------------------------------------------------------
// Launch
// ---------------------------------------------------------------------------
#define SMEM_LCV ((CH * PLANE + 2 * KK) * (int)sizeof(float))   // ~82.6KB

extern "C" void kernel_launch(void* const* d_in, const int* in_sizes, int n_in,
                              void* d_out, int out_size) {
    const float* ref  = (const float*)d_in[0];
    const float* beta = (const float*)d_in[2];
    const float* tw   = (const float*)d_in[3];
    const float* sw   = (const float*)d_in[4];
    const float* mw   = (const float*)d_in[5];
    const float* mrw  = (const float*)d_in[6];
    const float* mrb  = (const float*)d_in[7];
    const float* lrw  = (const float*)d_in[8];
    const float* lrb  = (const float*)d_in[9];
    const float* wreg = (const float*)d_in[10];
    const float* lst  = (const float*)d_in[11];

    cudaFuncSetAttribute(k_lcv<0>, cudaFuncAttributeMaxDynamicSharedMemorySize, SMEM_LCV);
    cudaFuncSetAttribute(k_lcv<1>, cudaFuncAttributeMaxDynamicSharedMemorySize, SMEM_LCV);
    cudaFuncSetAttribute(k_lcv<2>, cudaFuncAttributeMaxDynamicSharedMemorySize, SMEM_LCV);

    setup_consts<<<1, 128>>>(tw, sw, mw, wreg, lst);
    init_w<<<NPIX / 256, 256>>>(ref, beta);

    float* gw; cudaGetSymbolAddress((void**)&gw, g_w);
    float* gm; cudaGetSymbolAddress((void**)&gm, g_mapped);
    float* gf; cudaGetSymbolAddress((void**)&gf, g_fg);
    float* gc; cudaGetSymbolAddress((void**)&gc, g_c);
    float* gs; cudaGetSymbolAddress((void**)&gs, g_s);
    float* gv; cudaGetSymbolAddress((void**)&gv, g_cv2);

    dim3 grid(Wv / TBX, Hv / TBY, Bv);
    const int NT = NPIX / 2 / 256;   // 512 blocks for pair kernels

    // iter 1 cost volume of w
    k_lcv<0><<<grid, 128, SMEM_LCV>>>(gw, ref, gc, nullptr);

    for (int it = 0; it < 3; it++) {
        if (it == 0) k_act_fold<0><<<NT, 256>>>(mrw, mrb, gm);
        else         k_act_fold<1><<<NT, 256>>>(mrw, mrb, gm);
        k_lcv<0><<<grid, 128, SMEM_LCV>>>(gm, ref, gv, nullptr);
        k_foldB<<<NT, 256>>>(lrw, lrb);
        if (it < 2) k_lcv<1><<<grid, 128, SMEM_LCV>>>(gf, ref, gs, gw);
        else        k_lcv<2><<<grid, 128, SMEM_LCV>>>(gf, ref, gs, (float*)d_out);
    }
}

// round 5
// speedup vs baseline: 1.0918x; 1.0918x over previous
#include <cuda_runtime.h>
#include <math.h>

// Problem shape (fixed)
#define Bv 4
#define Hv 256
#define Wv 256
#define CH 32
#define NPIX (Bv*Hv*Wv)          // 262144
#define KK 81
#define NB 10

// Tile config: 128 threads -> 32x8 pixels (each thread: 2 adjacent pixels)
#define HALO 4
#define TBX 32
#define TBY 8
#define TW 40                    // TBX + 2*HALO
#define TH 16                    // TBY + 2*HALO
#define PLANE (TW*TH)            // 640

typedef unsigned long long ull;

// Static device scratch
__device__ float    g_w[(size_t)NPIX * CH];
__device__ float    g_mapped[(size_t)NPIX * CH];
__device__ float    g_fg[(size_t)NPIX * CH];
__device__ unsigned g_smask[6 * NPIX];   // 0..2 pos bits, 3..5 zero bits
__device__ float    g_A1[KK], g_A2[KK], g_Y[KK];  // a1=vp(1-a)/2, a2=vp(1+a)/2, Y=vp*y
__device__ float    g_scal[2];           // [0]=reg_weight, [1]=step_length

// ---------------- f32x2 helpers ----------------
__device__ __forceinline__ ull ffma2(ull a, ull b, ull c) {
    ull d; asm("fma.rn.f32x2 %0, %1, %2, %3;" : "=l"(d) : "l"(a), "l"(b), "l"(c)); return d;
}
__device__ __forceinline__ ull pack2(float x, float y) {
    ull d; asm("mov.b64 %0, {%1, %2};" : "=l"(d) : "f"(x), "f"(y)); return d;
}
__device__ __forceinline__ float2 unpack2(ull a) {
    float2 r; asm("mov.b64 {%0, %1}, %2;" : "=f"(r.x), "=f"(r.y) : "l"(a)); return r;
}
__device__ __forceinline__ ull lds64(unsigned addr) {
    ull d; asm volatile("ld.shared.b64 %0, [%1];" : "=l"(d) : "r"(addr)); return d;
}
__device__ __forceinline__ unsigned smem_u32(const void* p) {
    unsigned a;
    asm("{ .reg .u64 t; cvta.to.shared.u64 t, %1; cvt.u32.u64 %0, t; }" : "=r"(a) : "l"(p));
    return a;
}
__device__ __forceinline__ float sgnf(float x) {
    return (x > 0.f ? 1.f : 0.f) - (x < 0.f ? 1.f : 0.f);
}

// ---------------------------------------------------------------------------
__global__ void setup_consts(const float* __restrict__ tw,
                             const float* __restrict__ sw,
                             const float* __restrict__ mw,
                             const float* __restrict__ wreg,
                             const float* __restrict__ lstep) {
    int k = threadIdx.x;
    if (k < KK) {
        int i = k / 9, j = k % 9;
        float di = (float)(i - 4), dj = (float)(j - 4);
        float dist = sqrtf(di * di + dj * dj);
        float y = 0.f, vp = 0.f, m = 0.f;
        #pragma unroll
        for (int b = 0; b < NB; b++) {
            float t = dist * 2.0f - (float)b;
            float bv;
            if (i < 8) bv = fmaxf(0.f, 1.f - fabsf(t));
            else       bv = fminf(fmaxf(1.f + t, 0.f), 1.f);   // row-8 clip quirk
            y  += bv * tw[b];
            vp += bv * sw[b];
            m  += bv * mw[b];
        }
        float a = 1.f / (1.f + expf(-m));
        g_A1[k] = vp * 0.5f * (1.f - a);
        g_A2[k] = vp * 0.5f * (1.f + a);
        g_Y[k]  = vp * y;
    } else if (k == KK) {
        float r  = wreg[0] * wreg[0];
        float lo = (1e-5f * 1e-5f) / ((float)CH * (float)CH);
        g_scal[0] = fmaxf(r, lo);
        g_scal[1] = expf(lstep[0]);
    }
}

__global__ void init_w(const float* __restrict__ ref, const float* __restrict__ beta) {
    int p = blockIdx.x * blockDim.x + threadIdx.x;
    if (p >= NPIX) return;
    const float4* rp = (const float4*)(ref + (size_t)p * CH);
    float4 v[8];
    float ss = 0.f;
    #pragma unroll
    for (int i = 0; i < 8; i++) {
        v[i] = rp[i];
        ss += v[i].x * v[i].x + v[i].y * v[i].y + v[i].z * v[i].z + v[i].w * v[i].w;
    }
    float sc = beta[0] / (ss * (1.f / (float)CH) + 1e-6f);
    float4* wp = (float4*)(g_w + (size_t)p * CH);
    #pragma unroll
    for (int i = 0; i < 8; i++) {
        v[i].x *= sc; v[i].y *= sc; v[i].z *= sc; v[i].w *= sc;
        wp[i] = v[i];
    }
}

extern __shared__ float sdyn[];

// ---------------------------------------------------------------------------
// Shared pieces
// ---------------------------------------------------------------------------
__device__ __forceinline__ void load_tile(float* Rs, const float* __restrict__ ref,
                                          int b, int y0, int x0) {
    int tid = threadIdx.x;
    #pragma unroll
    for (int j = 0; j < PLANE / 128; j++) {     // 5
        int pix = tid + j * 128;
        int py = pix / TW, px = pix - py * TW;
        int gy = y0 - HALO + py, gx = x0 - HALO + px;
        bool ok = ((unsigned)gy < (unsigned)Hv) && ((unsigned)gx < (unsigned)Wv);
        const float4* rp = (const float4*)(ref + (ok ? (((size_t)(b * Hv + gy) * Wv) + gx) * CH : 0));
        #pragma unroll
        for (int q = 0; q < 8; q++) {
            float4 v;
            if (ok) v = rp[q]; else { v.x = v.y = v.z = v.w = 0.f; }
            Rs[(4 * q + 0) * PLANE + pix] = v.x;
            Rs[(4 * q + 1) * PLANE + pix] = v.y;
            Rs[(4 * q + 2) * PLANE + pix] = v.z;
            Rs[(4 * q + 3) * PLANE + pix] = v.w;
        }
    }
}

// Load pixel-pair src vectors packed as per-channel f32x2, optional sum of squares
__device__ __forceinline__ void load_pair(const float* __restrict__ src, int p0,
                                          ull* w2r, float* nx, float* ny) {
    const float4* s4 = (const float4*)(src + (size_t)p0 * CH);
    float ax = 0.f, ay = 0.f;
    #pragma unroll
    for (int q = 0; q < 8; q++) {
        float4 a = s4[q];
        float4 c = s4[q + 8];
        w2r[4 * q + 0] = pack2(a.x, c.x);
        w2r[4 * q + 1] = pack2(a.y, c.y);
        w2r[4 * q + 2] = pack2(a.z, c.z);
        w2r[4 * q + 3] = pack2(a.w, c.w);
        ax += a.x * a.x + a.y * a.y + a.z * a.z + a.w * a.w;
        ay += c.x * c.x + c.y * c.y + c.z * c.z + c.w * c.w;
    }
    if (nx) { *nx = ax; *ny = ay; }
}

// One row-shift of the pixel-pair dot: fills acc[9] (f32x2 accumulators)
__device__ __forceinline__ void dot_row(unsigned rb, const ull* w2r, ull* acc) {
    #pragma unroll
    for (int o = 0; o < 9; o++) acc[o] = 0ull;
    #pragma unroll 4
    for (int c = 0; c < CH; c++) {
        unsigned a = rb + (unsigned)(c * PLANE * 4);
        ull p0v = lds64(a);
        ull p1v = lds64(a + 8);
        ull p2v = lds64(a + 16);
        ull p3v = lds64(a + 24);
        ull p4v = lds64(a + 32);
        ull wv = w2r[c];
        acc[0] = ffma2(wv, p0v, acc[0]);
        acc[2] = ffma2(wv, p1v, acc[2]);
        acc[4] = ffma2(wv, p2v, acc[4]);
        acc[6] = ffma2(wv, p3v, acc[6]);
        acc[8] = ffma2(wv, p4v, acc[8]);
        float2 f0 = unpack2(p0v), f1 = unpack2(p1v), f2 = unpack2(p2v);
        float2 f3 = unpack2(p3v), f4 = unpack2(p4v);
        acc[1] = ffma2(wv, pack2(f0.y, f1.x), acc[1]);
        acc[3] = ffma2(wv, pack2(f1.y, f2.x), acc[3]);
        acc[5] = ffma2(wv, pack2(f2.y, f3.x), acc[5]);
        acc[7] = ffma2(wv, pack2(f3.y, f4.x), acc[7]);
    }
}

// ---------------------------------------------------------------------------
// Step A: c = LCV(w, ref); mapped = (dact*(act - Y)) @ mr_w + mr_b; store sign state
// ---------------------------------------------------------------------------
__global__ void __launch_bounds__(128)
k_stepA(const float* __restrict__ ref,
        const float* __restrict__ mr_w, const float* __restrict__ mr_b) {
    float* Rs  = sdyn;
    float* sM  = sdyn + CH * PLANE;
    float* sA1 = sM + KK * CH;
    float* sA2 = sA1 + KK;
    float* sY  = sA2 + KK;

    const int tid = threadIdx.x;
    const int b = blockIdx.z, y0 = blockIdx.y * TBY, x0 = blockIdx.x * TBX;
    load_tile(Rs, ref, b, y0, x0);
    for (int e = tid; e < KK * CH; e += 128) sM[e] = __ldg(mr_w + e);
    if (tid < KK) {
        sA1[tid] = g_A1[tid];
        sA2[tid] = g_A2[tid];
        sY[tid]  = g_Y[tid];
    }
    __syncthreads();

    const int txp = tid & 15, ty = tid >> 4;
    const int p0 = (b * Hv + (y0 + ty)) * Wv + (x0 + 2 * txp);

    ull w2r[CH];
    load_pair(g_w, p0, w2r, 0, 0);

    ull macc0[CH / 2], macc1[CH / 2];
    #pragma unroll
    for (int cp = 0; cp < CH / 2; cp++) {
        ull bb = pack2(__ldg(mr_b + 2 * cp), __ldg(mr_b + 2 * cp + 1));
        macc0[cp] = bb;
        macc1[cp] = bb;
    }

    const unsigned rs_base = smem_u32(Rs);
    const unsigned m_base  = smem_u32(sM);
    const float inv = 1.f / (float)CH;
    unsigned s0x = 0, s1x = 0, s2x = 0, z0x = 0, z1x = 0, z2x = 0;
    unsigned s0y = 0, s1y = 0, s2y = 0, z0y = 0, z1y = 0, z2y = 0;

    for (int di = 0; di < 9; di++) {
        ull acc[9];
        dot_row(rs_base + (unsigned)(((ty + di) * TW + 2 * txp) * 4), w2r, acc);
        #pragma unroll
        for (int o = 0; o < 9; o++) {
            int k = di * 9 + o;
            float2 r = unpack2(acc[o]);
            float cx = r.x * inv, cy = r.y * inv;
            float a1 = sA1[k], a2 = sA2[k], yk = sY[k];
            float sv0 = (a1 * sgnf(cx) + a2) * (a1 * fabsf(cx) + a2 * cx - yk);
            float sv1 = (a1 * sgnf(cy) + a2) * (a1 * fabsf(cy) + a2 * cy - yk);
            unsigned pbx = (cx > 0.f) ? 1u : 0u, zbx = (cx == 0.f) ? 1u : 0u;
            unsigned pby = (cy > 0.f) ? 1u : 0u, zby = (cy == 0.f) ? 1u : 0u;
            unsigned sh = (unsigned)k & 31u;
            if (k < 32)      { s0x |= pbx << sh; z0x |= zbx << sh; s0y |= pby << sh; z0y |= zby << sh; }
            else if (k < 64) { s1x |= pbx << sh; z1x |= zbx << sh; s1y |= pby << sh; z1y |= zby << sh; }
            else             { s2x |= pbx << sh; z2x |= zbx << sh; s2y |= pby << sh; z2y |= zby << sh; }
            ull v0 = pack2(sv0, sv0);
            ull v1 = pack2(sv1, sv1);
            unsigned mk = m_base + (unsigned)(k * CH * 4);
            #pragma unroll
            for (int cp = 0; cp < CH / 2; cp++) {
                ull m2 = lds64(mk + cp * 8);
                macc0[cp] = ffma2(v0, m2, macc0[cp]);
                macc1[cp] = ffma2(v1, m2, macc1[cp]);
            }
        }
    }

    #pragma unroll
    for (int cp = 0; cp < CH / 2; cp++) {
        *(float2*)(g_mapped + (size_t)p0 * CH + 2 * cp)       = unpack2(macc0[cp]);
        *(float2*)(g_mapped + (size_t)(p0 + 1) * CH + 2 * cp) = unpack2(macc1[cp]);
    }
    *(uint2*)(g_smask + p0)             = make_uint2(s0x, s0y);
    *(uint2*)(g_smask + NPIX + p0)      = make_uint2(s1x, s1y);
    *(uint2*)(g_smask + 2 * NPIX + p0)  = make_uint2(s2x, s2y);
    *(uint2*)(g_smask + 3 * NPIX + p0)  = make_uint2(z0x, z0y);
    *(uint2*)(g_smask + 4 * NPIX + p0)  = make_uint2(z1x, z1y);
    *(uint2*)(g_smask + 5 * NPIX + p0)  = make_uint2(z2x, z2y);
}

// ---------------------------------------------------------------------------
// Step B: fg = reg_weight * w + LCV(mapped, ref) @ lr_w + lr_b
// ---------------------------------------------------------------------------
__global__ void __launch_bounds__(128)
k_stepB(const float* __restrict__ ref,
        const float* __restrict__ lr_w, const float* __restrict__ lr_b) {
    float* Rs = sdyn;
    float* sM = sdyn + CH * PLANE;

    const int tid = threadIdx.x;
    const int b = blockIdx.z, y0 = blockIdx.y * TBY, x0 = blockIdx.x * TBX;
    load_tile(Rs, ref, b, y0, x0);
    for (int e = tid; e < KK * CH; e += 128) sM[e] = __ldg(lr_w + e);
    __syncthreads();

    const int txp = tid & 15, ty = tid >> 4;
    const int p0 = (b * Hv + (y0 + ty)) * Wv + (x0 + 2 * txp);

    ull w2r[CH];
    load_pair(g_mapped, p0, w2r, 0, 0);

    ull macc0[CH / 2], macc1[CH / 2];
    #pragma unroll
    for (int cp = 0; cp < CH / 2; cp++) {
        ull bb = pack2(__ldg(lr_b + 2 * cp), __ldg(lr_b + 2 * cp + 1));
        macc0[cp] = bb;
        macc1[cp] = bb;
    }

    const unsigned rs_base = smem_u32(Rs);
    const unsigned m_base  = smem_u32(sM);
    const float inv = 1.f / (float)CH;

    for (int di = 0; di < 9; di++) {
        ull acc[9];
        dot_row(rs_base + (unsigned)(((ty + di) * TW + 2 * txp) * 4), w2r, acc);
        #pragma unroll
        for (int o = 0; o < 9; o++) {
            int k = di * 9 + o;
            float2 r = unpack2(acc[o]);
            ull v0 = pack2(r.x * inv, r.x * inv);
            ull v1 = pack2(r.y * inv, r.y * inv);
            unsigned mk = m_base + (unsigned)(k * CH * 4);
            #pragma unroll
            for (int cp = 0; cp < CH / 2; cp++) {
                ull m2 = lds64(mk + cp * 8);
                macc0[cp] = ffma2(v0, m2, macc0[cp]);
                macc1[cp] = ffma2(v1, m2, macc1[cp]);
            }
        }
    }

    float reg = g_scal[0];
    #pragma unroll
    for (int cp = 0; cp < CH / 2; cp++) {
        float2 w0 = *(const float2*)(g_w + (size_t)p0 * CH + 2 * cp);
        float2 w1 = *(const float2*)(g_w + (size_t)(p0 + 1) * CH + 2 * cp);
        float2 m0 = unpack2(macc0[cp]);
        float2 m1 = unpack2(macc1[cp]);
        m0.x += reg * w0.x; m0.y += reg * w0.y;
        m1.x += reg * w1.x; m1.y += reg * w1.y;
        *(float2*)(g_fg + (size_t)p0 * CH + 2 * cp)       = m0;
        *(float2*)(g_fg + (size_t)(p0 + 1) * CH + 2 * cp) = m1;
    }
}

// ---------------------------------------------------------------------------
// Step C: den = sum_k (dact * LCV(fg,ref)_k)^2; alpha = sum(fg^2)/den * step;
//         w_out = w + alpha * fg
// ---------------------------------------------------------------------------
__global__ void __launch_bounds__(128)
k_stepC(const float* __restrict__ ref, float* __restrict__ wout) {
    float* Rs  = sdyn;
    float* sA1 = sdyn + CH * PLANE;
    float* sA2 = sA1 + KK;

    const int tid = threadIdx.x;
    const int b = blockIdx.z, y0 = blockIdx.y * TBY, x0 = blockIdx.x * TBX;
    load_tile(Rs, ref, b, y0, x0);
    if (tid < KK) {
        sA1[tid] = g_A1[tid];
        sA2[tid] = g_A2[tid];
    }
    __syncthreads();

    const int txp = tid & 15, ty = tid >> 4;
    const int p0 = (b * Hv + (y0 + ty)) * Wv + (x0 + 2 * txp);

    ull w2r[CH];
    float numx, numy;
    load_pair(g_fg, p0, w2r, &numx, &numy);

    uint2 s0 = *(const uint2*)(g_smask + p0);
    uint2 s1 = *(const uint2*)(g_smask + NPIX + p0);
    uint2 s2 = *(const uint2*)(g_smask + 2 * NPIX + p0);
    uint2 z0 = *(const uint2*)(g_smask + 3 * NPIX + p0);
    uint2 z1 = *(const uint2*)(g_smask + 4 * NPIX + p0);
    uint2 z2 = *(const uint2*)(g_smask + 5 * NPIX + p0);

    const unsigned rs_base = smem_u32(Rs);
    const float inv = 1.f / (float)CH;
    float denx = 0.f, deny = 0.f;

    for (int di = 0; di < 9; di++) {
        ull acc[9];
        dot_row(rs_base + (unsigned)(((ty + di) * TW + 2 * txp) * 4), w2r, acc);
        #pragma unroll
        for (int o = 0; o < 9; o++) {
            int k = di * 9 + o;
            float2 r = unpack2(acc[o]);
            float cx = r.x * inv, cy = r.y * inv;
            unsigned sh = (unsigned)k & 31u;
            unsigned px, zx, py, pz;
            if (k < 32)      { px = (s0.x >> sh) & 1u; zx = (z0.x >> sh) & 1u; py = (s0.y >> sh) & 1u; pz = (z0.y >> sh) & 1u; }
            else if (k < 64) { px = (s1.x >> sh) & 1u; zx = (z1.x >> sh) & 1u; py = (s1.y >> sh) & 1u; pz = (z1.y >> sh) & 1u; }
            else             { px = (s2.x >> sh) & 1u; zx = (z2.x >> sh) & 1u; py = (s2.y >> sh) & 1u; pz = (z2.y >> sh) & 1u; }
            float sgx = px ? 1.f : (zx ? 0.f : -1.f);
            float sgy = py ? 1.f : (pz ? 0.f : -1.f);
            float a1 = sA1[k], a2 = sA2[k];
            float t0 = (a1 * sgx + a2) * cx;
            float t1 = (a1 * sgy + a2) * cy;
            denx += t0 * t0;
            deny += t1 * t1;
        }
    }

    float st = g_scal[1];
    float as0 = numx / denx * st;
    float as1 = numy / deny * st;
    #pragma unroll
    for (int cp = 0; cp < CH / 2; cp++) {
        float2 w0 = *(const float2*)(g_w + (size_t)p0 * CH + 2 * cp);
        float2 w1 = *(const float2*)(g_w + (size_t)(p0 + 1) * CH + 2 * cp);
        float2 f0 = unpack2(w2r[cp]);          // channels 2cp, 2cp+1? no — w2r is per-channel pairs
        (void)f0;
        // reconstruct fg values for channels 2cp, 2cp+1 of both pixels
        float2 a = unpack2(w2r[2 * cp]);       // channel 2cp:   (pix0, pix1)
        float2 c = unpack2(w2r[2 * cp + 1]);   // channel 2cp+1: (pix0, pix1)
        w0.x += as0 * a.x; w0.y += as0 * c.x;
        w1.x += as1 * a.y; w1.y += as1 * c.y;
        *(float2*)(wout + (size_t)p0 * CH + 2 * cp)       = w0;
        *(float2*)(wout + (size_t)(p0 + 1) * CH + 2 * cp) = w1;
    }
}

// ---------------------------------------------------------------------------
#define SMEM_A ((CH*PLANE + KK*CH + 3*KK) * (int)sizeof(float))   // 93260
#define SMEM_B ((CH*PLANE + KK*CH) * (int)sizeof(float))          // 92288
#define SMEM_C ((CH*PLANE + 2*KK) * (int)sizeof(float))           // 82568

extern "C" void kernel_launch(void* const* d_in, const int* in_sizes, int n_in,
                              void* d_out, int out_size) {
    const float* ref  = (const float*)d_in[0];
    const float* beta = (const float*)d_in[2];
    const float* tw   = (const float*)d_in[3];
    const float* sw   = (const float*)d_in[4];
    const float* mw   = (const float*)d_in[5];
    const float* mrw  = (const float*)d_in[6];
    const float* mrb  = (const float*)d_in[7];
    const float* lrw  = (const float*)d_in[8];
    const float* lrb  = (const float*)d_in[9];
    const float* wreg = (const float*)d_in[10];
    const float* lst  = (const float*)d_in[11];

    cudaFuncSetAttribute(k_stepA, cudaFuncAttributeMaxDynamicSharedMemorySize, SMEM_A);
    cudaFuncSetAttribute(k_stepB, cudaFuncAttributeMaxDynamicSharedMemorySize, SMEM_B);
    cudaFuncSetAttribute(k_stepC, cudaFuncAttributeMaxDynamicSharedMemorySize, SMEM_C);

    setup_consts<<<1, 128>>>(tw, sw, mw, wreg, lst);
    init_w<<<NPIX / 256, 256>>>(ref, beta);

    float* gw; cudaGetSymbolAddress((void**)&gw, g_w);

    dim3 grid(Wv / TBX, Hv / TBY, Bv);
    for (int it = 0; it < 3; it++) {
        k_stepA<<<grid, 128, SMEM_A>>>(ref, mrw, mrb);
        k_stepB<<<grid, 128, SMEM_B>>>(ref, lrw, lrb);
        k_stepC<<<grid, 128, SMEM_C>>>(ref, it == 2 ? (float*)d_out : gw);
    }
}